// round 3
// baseline (speedup 1.0000x reference)
#include <cuda_runtime.h>
#include <math.h>

#define BB 2
#define DD 64
#define HH 96
#define WW 96
#define VOL (DD*HH*WW)          // 589824
#define NVOX (BB*VOL)           // 1179648
#define HWSZ (HH*WW)            // 9216
#define BIGF 1e10f
#define WT 32

#define NBLK3 (BB*HH*(WW/WT))   // 576 pass3 blocks

// Scratch (device globals: allocation-free per harness rules)
__device__ float g_fp2[NVOX];
__device__ float g_fn2[NVOX];
__device__ float g_pn[NBLK3];
__device__ float g_pd[NBLK3];

// Distance (in voxels) from position w (0..95) to the nearest set bit of the
// 96-bit row mask {lo: bits 0-63, hi: bits 64-95}. Returns huge if none.
__device__ __forceinline__ int nearest_bit(unsigned long long lo, unsigned hi, int w) {
    const int INF = 1 << 30;
    int up = INF, down = INF;
    if (w < 64) {
        unsigned long long a = lo >> w;
        if (a) up = __ffsll((long long)a) - 1;
        else if (hi) up = (64 - w) + (__ffs((int)hi) - 1);
        unsigned long long b = lo << (63 - w);
        if (b) down = __clzll((long long)b);
    } else {
        int w2 = w - 64;
        unsigned a = hi >> w2;
        if (a) up = __ffs((int)a) - 1;
        unsigned b = hi << (31 - w2);
        if (b) down = __clz((int)b);
        else if (lo) down = (w2 + 1) + __clzll((long long)lo);
    }
    return (up < down) ? up : down;
}

// Fused pass1 (along W, via bit scans) + pass2 (along H, in smem).
// One block per (b,d) plane. 512 threads.
__global__ __launch_bounds__(512) void k_passA(const float* __restrict__ tgt) {
    __shared__ unsigned smask[HH][3];
    __shared__ float s1[HH * WW];     // 36 KB

    int bd = blockIdx.x;
    int base = bd * HWSZ;
    int tid = threadIdx.x;
    int lane = tid & 31;
    int warp = tid >> 5;              // 0..15

    // Build row bit-masks: 96 rows x 3 segments = 288 warp-tasks.
    for (int task = warp; task < HH * 3; task += 16) {
        int h = task / 3, seg = task % 3;
        float v = tgt[base + h * WW + seg * 32 + lane];
        unsigned m = __ballot_sync(0xFFFFFFFFu, v > 0.5f);
        if (lane == 0) smask[h][seg] = m;
    }
    __syncthreads();

    // Two phases: 0 = fpos (distance to nearest 0), 1 = fneg (nearest 1).
    #pragma unroll 1
    for (int phase = 0; phase < 2; ++phase) {
        // pass1 into smem
        #pragma unroll 1
        for (int v = tid; v < HWSZ; v += 512) {
            int h = v / WW, w = v % WW;
            unsigned m0 = smask[h][0], m1 = smask[h][1], m2 = smask[h][2];
            unsigned long long lo = (unsigned long long)m0 | ((unsigned long long)m1 << 32);
            unsigned hi = m2;
            if (phase == 0) { lo = ~lo; hi = ~hi; }
            int d = nearest_bit(lo, hi, w);
            s1[v] = (d > 95) ? BIGF : (float)(d * d);
        }
        __syncthreads();

        // pass2 along H (rows of s1), exact windowed scan with early exit.
        float* gout = (phase == 0) ? g_fp2 : g_fn2;
        #pragma unroll 1
        for (int v = tid; v < HWSZ; v += 512) {
            int i = v / WW, w = v % WW;
            float bp = s1[v];
            #pragma unroll 1
            for (int k = 1; k < HH; ++k) {
                float k2 = (float)(k * k);
                if (k2 >= bp) break;
                int lo_ = i - k, hi_ = i + k;
                if (lo_ >= 0) bp = fminf(bp, s1[lo_ * WW + w] + k2);
                if (hi_ < HH) bp = fminf(bp, s1[hi_ * WW + w] + k2);
            }
            gout[base + v] = bp;
        }
        __syncthreads();
    }
}

// Pass3: along D in smem, fused loss epilogue, per-block partials.
__global__ __launch_bounds__(512) void k_pass3(const float* __restrict__ pred,
                                               const float* __restrict__ tgt) {
    __shared__ float sfp[DD][WT];
    __shared__ float sfn[DD][WT];
    __shared__ float rn[16], rd[16];

    int wt = blockIdx.x % (WW / WT);
    int bh = blockIdx.x / (WW / WT);
    int b = bh / HH;
    int h = bh % HH;
    int base = b * VOL + h * WW + wt * WT;
    int tid = threadIdx.x;

    #pragma unroll
    for (int r = tid; r < DD * WT; r += 512) {
        int d = r >> 5, w = r & 31;
        sfp[d][w] = g_fp2[base + d * HWSZ + w];
        sfn[d][w] = g_fn2[base + d * HWSZ + w];
    }
    __syncthreads();

    int w = tid & 31;
    int d0 = tid >> 5;  // 0..15
    float accn = 0.0f, accd = 0.0f;

    #pragma unroll 1
    for (int i = d0; i < DD; i += 16) {
        float bp = sfp[i][w];
        float bn = sfn[i][w];
        #pragma unroll 1
        for (int k = 1; k < DD; ++k) {
            float k2 = (float)(k * k);
            if (k2 >= bp && k2 >= bn) break;
            int lo = i - k, hi = i + k;
            if (lo >= 0) {
                bp = fminf(bp, sfp[lo][w] + k2);
                bn = fminf(bn, sfn[lo][w] + k2);
            }
            if (hi < DD) {
                bp = fminf(bp, sfp[hi][w] + k2);
                bn = fminf(bn, sfn[hi][w] + k2);
            }
        }
        float dp = sqrtf(bp);
        float dn = sqrtf(bn);
        float a = fabsf(dn - dp);
        float wgt = (a <= 3.0f) ? 1.0f : ((a >= 5.0f) ? 0.0f : (1.0f - (a - 3.0f) * 0.5f));

        int idx = base + i * HWSZ + w;
        float p = pred[idx];
        float t = tgt[idx];
        float lp  = fmaxf(__logf(p), -100.0f);
        float l1p = fmaxf(__logf(1.0f - p), -100.0f);
        float bce = -(t * lp + (1.0f - t) * l1p);
        accn += bce * wgt;
        accd += wgt;
    }

    #pragma unroll
    for (int off = 16; off > 0; off >>= 1) {
        accn += __shfl_down_sync(0xFFFFFFFFu, accn, off);
        accd += __shfl_down_sync(0xFFFFFFFFu, accd, off);
    }
    if (w == 0) { rn[d0] = accn; rd[d0] = accd; }
    __syncthreads();
    if (tid == 0) {
        float sn = 0.0f, sd = 0.0f;
        #pragma unroll
        for (int j = 0; j < 16; ++j) { sn += rn[j]; sd += rd[j]; }
        g_pn[blockIdx.x] = sn;   // fully overwritten every call: no zeroing needed
        g_pd[blockIdx.x] = sd;
    }
}

// Final: reduce 576 partials (288 per batch) -> scalar.
__global__ void k_final(float* __restrict__ out) {
    __shared__ double wn[8], wd[8];
    int tid = threadIdx.x;            // 256 threads
    int b = tid >> 7;                 // 0..1
    int j0 = tid & 127;
    double an = 0.0, ad = 0.0;
    const int PER_B = NBLK3 / BB;     // 288
    for (int j = j0; j < PER_B; j += 128) {
        an += (double)g_pn[b * PER_B + j];
        ad += (double)g_pd[b * PER_B + j];
    }
    #pragma unroll
    for (int off = 16; off > 0; off >>= 1) {
        an += __shfl_down_sync(0xFFFFFFFFu, an, off);
        ad += __shfl_down_sync(0xFFFFFFFFu, ad, off);
    }
    int warp = tid >> 5, lane = tid & 31;
    if (lane == 0) { wn[warp] = an; wd[warp] = ad; }
    __syncthreads();
    if (tid == 0) {
        double num0 = wn[0] + wn[1] + wn[2] + wn[3];
        double den0 = wd[0] + wd[1] + wd[2] + wd[3];
        double num1 = wn[4] + wn[5] + wn[6] + wn[7];
        double den1 = wd[4] + wd[5] + wd[6] + wd[7];
        double acc = num0 / (den0 + 1e-5) + num1 / (den1 + 1e-5);
        out[0] = (float)(acc / (double)BB);
    }
}

extern "C" void kernel_launch(void* const* d_in, const int* in_sizes, int n_in,
                              void* d_out, int out_size) {
    const float* pred = (const float*)d_in[0];
    const float* tgt  = (const float*)d_in[1];
    (void)in_sizes; (void)n_in; (void)out_size;

    k_passA<<<BB * DD, 512>>>(tgt);            // 128 blocks
    k_pass3<<<NBLK3, 512>>>(pred, tgt);        // 576 blocks
    k_final<<<1, 256>>>((float*)d_out);
}

// round 4
// speedup vs baseline: 1.0525x; 1.0525x over previous
#include <cuda_runtime.h>
#include <math.h>

#define BB 2
#define DD 64
#define HH 96
#define WW 96
#define VOL (DD*HH*WW)          // 589824
#define NVOX (BB*VOL)           // 1179648
#define HWSZ (HH*WW)            // 9216
#define NPLANE (BB*DD)          // 128
#define BIGF 1e10f
#define WT 32

#define NBLK3 (BB*HH*(WW/WT))   // 576 pass3 blocks

// Scratch (device globals: allocation-free per harness rules)
__device__ unsigned g_mask[NPLANE][HH][3];
__device__ float g_fp2[NVOX];
__device__ float g_fn2[NVOX];
__device__ float g_pn[NBLK3];
__device__ float g_pd[NBLK3];

// Distance (voxels) from w (0..95) to nearest set bit of the 96-bit row mask
// {lo: bits 0-63, hi: bits 64-95}. Returns huge if none.
__device__ __forceinline__ int nearest_bit(unsigned long long lo, unsigned hi, int w) {
    const int INF = 1 << 30;
    int up = INF, down = INF;
    if (w < 64) {
        unsigned long long a = lo >> w;
        if (a) up = __ffsll((long long)a) - 1;
        else if (hi) up = (64 - w) + (__ffs((int)hi) - 1);
        unsigned long long b = lo << (63 - w);
        if (b) down = __clzll((long long)b);
    } else {
        int w2 = w - 64;
        unsigned a = hi >> w2;
        if (a) up = __ffs((int)a) - 1;
        unsigned b = hi << (31 - w2);
        if (b) down = __clz((int)b);
        else if (lo) down = (w2 + 1) + __clzll((long long)lo);
    }
    return (up < down) ? up : down;
}

// Build 96-bit row masks: one warp per (plane,row,seg).
__global__ __launch_bounds__(256) void k_mask(const float* __restrict__ tgt) {
    int gw = (blockIdx.x * 256 + threadIdx.x) >> 5;    // 0..36863
    int lane = threadIdx.x & 31;
    int seg = gw % 3;
    int rest = gw / 3;
    int h = rest % HH;
    int bd = rest / HH;
    float v = tgt[bd * HWSZ + h * WW + seg * 32 + lane];
    unsigned m = __ballot_sync(0xFFFFFFFFu, v > 0.5f);
    if (lane == 0) g_mask[bd][h][seg] = m;
}

// Fused pass1 (bit-scan along W) + pass2 (early-exit scan along H, in smem).
// Block = (plane, phase, w-tile). 256 threads.
__global__ __launch_bounds__(256) void k_passBC() {
    __shared__ unsigned smask[HH][3];
    __shared__ float s1[HH][WT];

    int blk = blockIdx.x;
    int wt = blk % 3;
    int phase = (blk / 3) & 1;
    int bd = blk / 6;
    int base = bd * HWSZ;
    int tid = threadIdx.x;

    // Load this plane's masks (288 words).
    if (tid < HH * 3) ((unsigned*)smask)[tid] = ((const unsigned*)g_mask[bd])[tid];
    __syncthreads();

    // pass1: exact distance along W via bit scan; 12 voxels per thread.
    #pragma unroll
    for (int v = tid; v < HH * WT; v += 256) {
        int h = v >> 5;
        int wl = v & 31;
        int w = wt * WT + wl;
        unsigned long long lo = (unsigned long long)smask[h][0]
                              | ((unsigned long long)smask[h][1] << 32);
        unsigned hi = smask[h][2];
        if (phase == 0) { lo = ~lo; hi = ~hi; }   // fpos: nearest 0
        int d = nearest_bit(lo, hi, w);
        s1[h][wl] = (d > 95) ? BIGF : (float)(d * d);
    }
    __syncthreads();

    // pass2 along H: out[i] = min_k s1[i±k] + k^2, early exit when k^2 >= best.
    float* gout = (phase == 0) ? g_fp2 : g_fn2;
    #pragma unroll 1
    for (int v = tid; v < HH * WT; v += 256) {
        int i = v >> 5;
        int wl = v & 31;
        float bp = s1[i][wl];
        #pragma unroll 1
        for (int k = 1; k < HH; ++k) {
            float k2 = (float)(k * k);
            if (k2 >= bp) break;
            int lo_ = i - k, hi_ = i + k;
            if (lo_ >= 0) bp = fminf(bp, s1[lo_][wl] + k2);
            if (hi_ < HH) bp = fminf(bp, s1[hi_][wl] + k2);
        }
        gout[base + i * WW + wt * WT + wl] = bp;   // coalesced per warp
    }
}

// Pass3: along D in smem, fused loss epilogue, per-block partials.
__global__ __launch_bounds__(512) void k_pass3(const float* __restrict__ pred,
                                               const float* __restrict__ tgt) {
    __shared__ float sfp[DD][WT];
    __shared__ float sfn[DD][WT];
    __shared__ float rn[16], rd[16];

    int wt = blockIdx.x % (WW / WT);
    int bh = blockIdx.x / (WW / WT);
    int b = bh / HH;
    int h = bh % HH;
    int base = b * VOL + h * WW + wt * WT;
    int tid = threadIdx.x;

    #pragma unroll
    for (int r = tid; r < DD * WT; r += 512) {
        int d = r >> 5, w = r & 31;
        sfp[d][w] = g_fp2[base + d * HWSZ + w];
        sfn[d][w] = g_fn2[base + d * HWSZ + w];
    }
    __syncthreads();

    int w = tid & 31;
    int d0 = tid >> 5;  // 0..15
    float accn = 0.0f, accd = 0.0f;

    #pragma unroll 1
    for (int i = d0; i < DD; i += 16) {
        float bp = sfp[i][w];
        float bn = sfn[i][w];
        #pragma unroll 1
        for (int k = 1; k < DD; ++k) {
            float k2 = (float)(k * k);
            if (k2 >= bp && k2 >= bn) break;
            int lo = i - k, hi = i + k;
            if (lo >= 0) {
                bp = fminf(bp, sfp[lo][w] + k2);
                bn = fminf(bn, sfn[lo][w] + k2);
            }
            if (hi < DD) {
                bp = fminf(bp, sfp[hi][w] + k2);
                bn = fminf(bn, sfn[hi][w] + k2);
            }
        }
        float dp = sqrtf(bp);
        float dn = sqrtf(bn);
        float a = fabsf(dn - dp);
        float wgt = (a <= 3.0f) ? 1.0f : ((a >= 5.0f) ? 0.0f : (1.0f - (a - 3.0f) * 0.5f));

        int idx = base + i * HWSZ + w;
        float p = pred[idx];
        float t = tgt[idx];
        float lp  = fmaxf(__logf(p), -100.0f);
        float l1p = fmaxf(__logf(1.0f - p), -100.0f);
        float bce = -(t * lp + (1.0f - t) * l1p);
        accn += bce * wgt;
        accd += wgt;
    }

    #pragma unroll
    for (int off = 16; off > 0; off >>= 1) {
        accn += __shfl_down_sync(0xFFFFFFFFu, accn, off);
        accd += __shfl_down_sync(0xFFFFFFFFu, accd, off);
    }
    if (w == 0) { rn[d0] = accn; rd[d0] = accd; }
    __syncthreads();
    if (tid == 0) {
        float sn = 0.0f, sd = 0.0f;
        #pragma unroll
        for (int j = 0; j < 16; ++j) { sn += rn[j]; sd += rd[j]; }
        g_pn[blockIdx.x] = sn;   // fully overwritten every call: no zeroing needed
        g_pd[blockIdx.x] = sd;
    }
}

// Final: reduce 576 partials (288 per batch) -> scalar.
__global__ void k_final(float* __restrict__ out) {
    __shared__ double wn[8], wd[8];
    int tid = threadIdx.x;            // 256 threads
    int b = tid >> 7;
    int j0 = tid & 127;
    double an = 0.0, ad = 0.0;
    const int PER_B = NBLK3 / BB;     // 288
    for (int j = j0; j < PER_B; j += 128) {
        an += (double)g_pn[b * PER_B + j];
        ad += (double)g_pd[b * PER_B + j];
    }
    #pragma unroll
    for (int off = 16; off > 0; off >>= 1) {
        an += __shfl_down_sync(0xFFFFFFFFu, an, off);
        ad += __shfl_down_sync(0xFFFFFFFFu, ad, off);
    }
    int warp = tid >> 5, lane = tid & 31;
    if (lane == 0) { wn[warp] = an; wd[warp] = ad; }
    __syncthreads();
    if (tid == 0) {
        double num0 = wn[0] + wn[1] + wn[2] + wn[3];
        double den0 = wd[0] + wd[1] + wd[2] + wd[3];
        double num1 = wn[4] + wn[5] + wn[6] + wn[7];
        double den1 = wd[4] + wd[5] + wd[6] + wd[7];
        double acc = num0 / (den0 + 1e-5) + num1 / (den1 + 1e-5);
        out[0] = (float)(acc / (double)BB);
    }
}

extern "C" void kernel_launch(void* const* d_in, const int* in_sizes, int n_in,
                              void* d_out, int out_size) {
    const float* pred = (const float*)d_in[0];
    const float* tgt  = (const float*)d_in[1];
    (void)in_sizes; (void)n_in; (void)out_size;

    k_mask<<<NVOX / 256, 256>>>(tgt);          // 4608 blocks
    k_passBC<<<NPLANE * 2 * 3, 256>>>();       // 768 blocks
    k_pass3<<<NBLK3, 512>>>(pred, tgt);        // 576 blocks
    k_final<<<1, 256>>>((float*)d_out);
}

// round 5
// speedup vs baseline: 1.1232x; 1.0672x over previous
#include <cuda_runtime.h>
#include <math.h>

#define BB 2
#define DD 64
#define HH 96
#define WW 96
#define VOL (DD*HH*WW)          // 589824
#define NVOX (BB*VOL)           // 1179648
#define HWSZ (HH*WW)            // 9216
#define NPLANE (BB*DD)          // 128
#define BIGF 1e10f
#define WT 32

#define NBLK3 (BB*HH*(WW/WT))   // 576 pass3 blocks

// Scratch (device globals: allocation-free per harness rules)
__device__ unsigned g_mask[NPLANE][HH][3];
__device__ float g_fp2[NVOX];
__device__ float g_fn2[NVOX];
__device__ volatile float g_pn[NBLK3];
__device__ volatile float g_pd[NBLK3];
__device__ unsigned g_count;    // zero-init; last block resets to 0 -> deterministic replays

// Distance (voxels) from w (0..95) to nearest set bit of the 96-bit row mask
// {lo: bits 0-63, hi: bits 64-95}. Returns huge if none.
__device__ __forceinline__ int nearest_bit(unsigned long long lo, unsigned hi, int w) {
    const int INF = 1 << 30;
    int up = INF, down = INF;
    if (w < 64) {
        unsigned long long a = lo >> w;
        if (a) up = __ffsll((long long)a) - 1;
        else if (hi) up = (64 - w) + (__ffs((int)hi) - 1);
        unsigned long long b = lo << (63 - w);
        if (b) down = __clzll((long long)b);
    } else {
        int w2 = w - 64;
        unsigned a = hi >> w2;
        if (a) up = __ffs((int)a) - 1;
        unsigned b = hi << (31 - w2);
        if (b) down = __clz((int)b);
        else if (lo) down = (w2 + 1) + __clzll((long long)lo);
    }
    return (up < down) ? up : down;
}

// Build 96-bit row masks: one warp per (plane,row,seg).
__global__ __launch_bounds__(256) void k_mask(const float* __restrict__ tgt) {
    int gw = (blockIdx.x * 256 + threadIdx.x) >> 5;    // 0..36863
    int lane = threadIdx.x & 31;
    int seg = gw % 3;
    int rest = gw / 3;
    int h = rest % HH;
    int bd = rest / HH;
    float v = tgt[bd * HWSZ + h * WW + seg * 32 + lane];
    unsigned m = __ballot_sync(0xFFFFFFFFu, v > 0.5f);
    if (lane == 0) g_mask[bd][h][seg] = m;
}

// Fused pass1 (bit-scan along W) + pass2 (early-exit scan along H, in smem).
// Block = (plane, phase, w-tile). 256 threads.
__global__ __launch_bounds__(256) void k_passBC() {
    __shared__ unsigned smask[HH][3];
    __shared__ float s1[HH][WT];

    int blk = blockIdx.x;
    int wt = blk % 3;
    int phase = (blk / 3) & 1;
    int bd = blk / 6;
    int base = bd * HWSZ;
    int tid = threadIdx.x;

    // Load this plane's masks (288 words) -- strided: 256 threads < 288 words!
    #pragma unroll
    for (int j = tid; j < HH * 3; j += 256)
        ((unsigned*)smask)[j] = ((const unsigned*)g_mask[bd])[j];
    __syncthreads();

    // pass1: exact distance along W via bit scan; 12 voxels per thread.
    #pragma unroll
    for (int v = tid; v < HH * WT; v += 256) {
        int h = v >> 5;
        int wl = v & 31;
        int w = wt * WT + wl;
        unsigned long long lo = (unsigned long long)smask[h][0]
                              | ((unsigned long long)smask[h][1] << 32);
        unsigned hi = smask[h][2];
        if (phase == 0) { lo = ~lo; hi = ~hi; }   // fpos: nearest 0
        int d = nearest_bit(lo, hi, w);
        s1[h][wl] = (d > 95) ? BIGF : (float)(d * d);
    }
    __syncthreads();

    // pass2 along H: out[i] = min_k s1[i±k] + k^2, early exit when k^2 >= best.
    float* gout = (phase == 0) ? g_fp2 : g_fn2;
    #pragma unroll 1
    for (int v = tid; v < HH * WT; v += 256) {
        int i = v >> 5;
        int wl = v & 31;
        float bp = s1[i][wl];
        #pragma unroll 1
        for (int k = 1; k < HH; ++k) {
            float k2 = (float)(k * k);
            if (k2 >= bp) break;
            int lo_ = i - k, hi_ = i + k;
            if (lo_ >= 0) bp = fminf(bp, s1[lo_][wl] + k2);
            if (hi_ < HH) bp = fminf(bp, s1[hi_][wl] + k2);
        }
        gout[base + i * WW + wt * WT + wl] = bp;   // coalesced per warp
    }
}

// Pass3: along D in smem, fused loss epilogue, per-block partials,
// with final reduction fused via last-block-done.
__global__ __launch_bounds__(512) void k_pass3(const float* __restrict__ pred,
                                               const float* __restrict__ tgt,
                                               float* __restrict__ out) {
    __shared__ float sfp[DD][WT];
    __shared__ float sfn[DD][WT];
    __shared__ float rn[16], rd[16];
    __shared__ int s_last;

    int wt = blockIdx.x % (WW / WT);
    int bh = blockIdx.x / (WW / WT);
    int b = bh / HH;
    int h = bh % HH;
    int base = b * VOL + h * WW + wt * WT;
    int tid = threadIdx.x;

    #pragma unroll
    for (int r = tid; r < DD * WT; r += 512) {
        int d = r >> 5, w = r & 31;
        sfp[d][w] = g_fp2[base + d * HWSZ + w];
        sfn[d][w] = g_fn2[base + d * HWSZ + w];
    }
    __syncthreads();

    int w = tid & 31;
    int d0 = tid >> 5;  // 0..15
    float accn = 0.0f, accd = 0.0f;

    #pragma unroll 1
    for (int i = d0; i < DD; i += 16) {
        float bp = sfp[i][w];
        float bn = sfn[i][w];
        #pragma unroll 1
        for (int k = 1; k < DD; ++k) {
            float k2 = (float)(k * k);
            if (k2 >= bp && k2 >= bn) break;
            int lo = i - k, hi = i + k;
            if (lo >= 0) {
                bp = fminf(bp, sfp[lo][w] + k2);
                bn = fminf(bn, sfn[lo][w] + k2);
            }
            if (hi < DD) {
                bp = fminf(bp, sfp[hi][w] + k2);
                bn = fminf(bn, sfn[hi][w] + k2);
            }
        }
        float dp = sqrtf(bp);
        float dn = sqrtf(bn);
        float a = fabsf(dn - dp);
        float wgt = (a <= 3.0f) ? 1.0f : ((a >= 5.0f) ? 0.0f : (1.0f - (a - 3.0f) * 0.5f));

        int idx = base + i * HWSZ + w;
        float p = pred[idx];
        float t = tgt[idx];
        float lp  = fmaxf(__logf(p), -100.0f);
        float l1p = fmaxf(__logf(1.0f - p), -100.0f);
        float bce = -(t * lp + (1.0f - t) * l1p);
        accn += bce * wgt;
        accd += wgt;
    }

    #pragma unroll
    for (int off = 16; off > 0; off >>= 1) {
        accn += __shfl_down_sync(0xFFFFFFFFu, accn, off);
        accd += __shfl_down_sync(0xFFFFFFFFu, accd, off);
    }
    if (w == 0) { rn[d0] = accn; rd[d0] = accd; }
    __syncthreads();
    if (tid == 0) {
        float sn = 0.0f, sd = 0.0f;
        #pragma unroll
        for (int j = 0; j < 16; ++j) { sn += rn[j]; sd += rd[j]; }
        g_pn[blockIdx.x] = sn;
        g_pd[blockIdx.x] = sd;
        __threadfence();
        unsigned old = atomicAdd(&g_count, 1u);
        s_last = (old == NBLK3 - 1) ? 1 : 0;
    }
    __syncthreads();

    // Last block: reduce all 576 partials -> scalar, reset counter.
    if (s_last) {
        __shared__ double wn[16], wd[16];
        const int PER_B = NBLK3 / BB;     // 288
        int rb = tid >> 8;                // 0..1 (batch)
        int j0 = tid & 255;
        double an = 0.0, ad = 0.0;
        #pragma unroll
        for (int j = j0; j < PER_B; j += 256) {
            an += (double)g_pn[rb * PER_B + j];
            ad += (double)g_pd[rb * PER_B + j];
        }
        #pragma unroll
        for (int off = 16; off > 0; off >>= 1) {
            an += __shfl_down_sync(0xFFFFFFFFu, an, off);
            ad += __shfl_down_sync(0xFFFFFFFFu, ad, off);
        }
        int warp = tid >> 5, lane = tid & 31;
        if (lane == 0) { wn[warp] = an; wd[warp] = ad; }
        __syncthreads();
        if (tid == 0) {
            double n0 = 0.0, d0_ = 0.0, n1 = 0.0, d1 = 0.0;
            #pragma unroll
            for (int j = 0; j < 8; ++j)  { n0 += wn[j]; d0_ += wd[j]; }
            #pragma unroll
            for (int j = 8; j < 16; ++j) { n1 += wn[j]; d1 += wd[j]; }
            double acc = n0 / (d0_ + 1e-5) + n1 / (d1 + 1e-5);
            out[0] = (float)(acc / (double)BB);
            g_count = 0;   // reset for next graph replay (deterministic)
        }
    }
}

extern "C" void kernel_launch(void* const* d_in, const int* in_sizes, int n_in,
                              void* d_out, int out_size) {
    const float* pred = (const float*)d_in[0];
    const float* tgt  = (const float*)d_in[1];
    (void)in_sizes; (void)n_in; (void)out_size;

    k_mask<<<NVOX / 256, 256>>>(tgt);               // 4608 blocks
    k_passBC<<<NPLANE * 2 * 3, 256>>>();            // 768 blocks
    k_pass3<<<NBLK3, 512>>>(pred, tgt, (float*)d_out);  // 576 blocks, final fused
}

// round 6
// speedup vs baseline: 1.1598x; 1.0326x over previous
#include <cuda_runtime.h>
#include <math.h>

#define BB 2
#define DD 64
#define HH 96
#define WW 96
#define VOL (DD*HH*WW)          // 589824
#define NVOX (BB*VOL)           // 1179648
#define HWSZ (HH*WW)            // 9216
#define NPLANE (BB*DD)          // 128
#define BIGF 1e10f
#define WT 32

#define NBLK3 (BB*HH*(WW/WT))   // 576 pass3 blocks

// Scratch (device globals: allocation-free per harness rules)
__device__ float2 g_f2[NVOX];             // {fpos, fneg} after W+H transform
__device__ volatile float g_pn[NBLK3];
__device__ volatile float g_pd[NBLK3];
__device__ unsigned g_count;              // zero-init; last block resets -> deterministic

// Distance (voxels) from w (0..95) to nearest set bit of the 96-bit row mask
// {lo: bits 0-63, hi: bits 64-95}. Returns huge if none.
__device__ __forceinline__ int nearest_bit(unsigned long long lo, unsigned hi, int w) {
    const int INF = 1 << 30;
    int up = INF, down = INF;
    if (w < 64) {
        unsigned long long a = lo >> w;
        if (a) up = __ffsll((long long)a) - 1;
        else if (hi) up = (64 - w) + (__ffs((int)hi) - 1);
        unsigned long long b = lo << (63 - w);
        if (b) down = __clzll((long long)b);
    } else {
        int w2 = w - 64;
        unsigned a = hi >> w2;
        if (a) up = __ffs((int)a) - 1;
        unsigned b = hi << (31 - w2);
        if (b) down = __clz((int)b);
        else if (lo) down = (w2 + 1) + __clzll((long long)lo);
    }
    return (up < down) ? up : down;
}

// Fused: mask build (ballot) + pass1 (bit-scan along W, both phases)
// + pass2 (joint early-exit scan along H in smem). Block = (plane, w-tile).
__global__ __launch_bounds__(256) void k_passBC(const float* __restrict__ tgt) {
    __shared__ unsigned smask[HH][3];
    __shared__ float s1p[HH][WT];
    __shared__ float s1n[HH][WT];

    int wt = blockIdx.x % 3;
    int bd = blockIdx.x / 3;
    int base = bd * HWSZ;
    int tid = threadIdx.x;
    int lane = tid & 31;
    int warp = tid >> 5;              // 0..7

    // Build this plane's row masks: 288 warp-tasks over 8 warps (36 each).
    #pragma unroll 4
    for (int task = warp; task < HH * 3; task += 8) {
        int h = task / 3, seg = task % 3;
        float v = tgt[base + h * WW + seg * 32 + lane];
        unsigned m = __ballot_sync(0xFFFFFFFFu, v > 0.5f);
        if (lane == 0) smask[h][seg] = m;
    }
    __syncthreads();

    // pass1: exact distance along W via bit scan; both phases.
    #pragma unroll 1
    for (int v = tid; v < HH * WT; v += 256) {
        int h = v >> 5;
        int wl = v & 31;
        int w = wt * WT + wl;
        unsigned long long lo = (unsigned long long)smask[h][0]
                              | ((unsigned long long)smask[h][1] << 32);
        unsigned hi = smask[h][2];
        int dn = nearest_bit(lo, hi, w);        // nearest 1
        int dp = nearest_bit(~lo, ~hi, w);      // nearest 0
        s1p[h][wl] = (dp > 95) ? BIGF : (float)(dp * dp);
        s1n[h][wl] = (dn > 95) ? BIGF : (float)(dn * dn);
    }
    __syncthreads();

    // pass2 along H: joint early-exit windowed scan; write float2 coalesced.
    #pragma unroll 1
    for (int v = tid; v < HH * WT; v += 256) {
        int i = v >> 5;
        int wl = v & 31;
        float bp = s1p[i][wl];
        float bn = s1n[i][wl];
        #pragma unroll 1
        for (int k = 1; k < HH; ++k) {
            float k2 = (float)(k * k);
            if (k2 >= bp && k2 >= bn) break;
            int lo_ = i - k, hi_ = i + k;
            if (lo_ >= 0) {
                bp = fminf(bp, s1p[lo_][wl] + k2);
                bn = fminf(bn, s1n[lo_][wl] + k2);
            }
            if (hi_ < HH) {
                bp = fminf(bp, s1p[hi_][wl] + k2);
                bn = fminf(bn, s1n[hi_][wl] + k2);
            }
        }
        g_f2[base + i * WW + wt * WT + wl] = make_float2(bp, bn);
    }
}

// Pass3: along D in smem, fused loss epilogue + grid-final reduction.
__global__ __launch_bounds__(512) void k_pass3(const float* __restrict__ pred,
                                               const float* __restrict__ tgt,
                                               float* __restrict__ out) {
    __shared__ float sfp[DD][WT];
    __shared__ float sfn[DD][WT];
    __shared__ float rn[16], rd[16];
    __shared__ int s_last;

    int wt = blockIdx.x % (WW / WT);
    int bh = blockIdx.x / (WW / WT);
    int b = bh / HH;
    int h = bh % HH;
    int base = b * VOL + h * WW + wt * WT;
    int tid = threadIdx.x;

    #pragma unroll
    for (int r = tid; r < DD * WT; r += 512) {
        int d = r >> 5, w = r & 31;
        float2 v = g_f2[base + d * HWSZ + w];
        sfp[d][w] = v.x;
        sfn[d][w] = v.y;
    }

    int w = tid & 31;
    int d0 = tid >> 5;  // 0..15

    // Prefetch pred/target for this thread's 4 voxels (hides DRAM latency
    // behind the smem scan loop below).
    float pv[4], tv[4];
    #pragma unroll
    for (int j = 0; j < 4; ++j) {
        int idx = base + (d0 + 16 * j) * HWSZ + w;
        pv[j] = pred[idx];
        tv[j] = tgt[idx];
    }
    __syncthreads();

    float accn = 0.0f, accd = 0.0f;
    #pragma unroll 1
    for (int j = 0; j < 4; ++j) {
        int i = d0 + 16 * j;
        float bp = sfp[i][w];
        float bn = sfn[i][w];
        #pragma unroll 1
        for (int k = 1; k < DD; ++k) {
            float k2 = (float)(k * k);
            if (k2 >= bp && k2 >= bn) break;
            int lo = i - k, hi = i + k;
            if (lo >= 0) {
                bp = fminf(bp, sfp[lo][w] + k2);
                bn = fminf(bn, sfn[lo][w] + k2);
            }
            if (hi < DD) {
                bp = fminf(bp, sfp[hi][w] + k2);
                bn = fminf(bn, sfn[hi][w] + k2);
            }
        }
        float dp = sqrtf(bp);
        float dn = sqrtf(bn);
        float a = fabsf(dn - dp);
        float wgt = (a <= 3.0f) ? 1.0f : ((a >= 5.0f) ? 0.0f : (1.0f - (a - 3.0f) * 0.5f));

        float lp  = fmaxf(__logf(pv[j]), -100.0f);
        float l1p = fmaxf(__logf(1.0f - pv[j]), -100.0f);
        float bce = -(tv[j] * lp + (1.0f - tv[j]) * l1p);
        accn += bce * wgt;
        accd += wgt;
    }

    #pragma unroll
    for (int off = 16; off > 0; off >>= 1) {
        accn += __shfl_down_sync(0xFFFFFFFFu, accn, off);
        accd += __shfl_down_sync(0xFFFFFFFFu, accd, off);
    }
    if (w == 0) { rn[d0] = accn; rd[d0] = accd; }
    __syncthreads();
    if (tid == 0) {
        float sn = 0.0f, sd = 0.0f;
        #pragma unroll
        for (int j = 0; j < 16; ++j) { sn += rn[j]; sd += rd[j]; }
        g_pn[blockIdx.x] = sn;
        g_pd[blockIdx.x] = sd;
        __threadfence();
        unsigned old = atomicAdd(&g_count, 1u);
        s_last = (old == NBLK3 - 1) ? 1 : 0;
    }
    __syncthreads();

    // Last block: reduce all 576 partials -> scalar, reset counter.
    if (s_last) {
        __shared__ double wn[16], wd[16];
        const int PER_B = NBLK3 / BB;     // 288
        int rb = tid >> 8;                // 0..1 (batch)
        int j0 = tid & 255;
        double an = 0.0, ad = 0.0;
        #pragma unroll
        for (int j = j0; j < PER_B; j += 256) {
            an += (double)g_pn[rb * PER_B + j];
            ad += (double)g_pd[rb * PER_B + j];
        }
        #pragma unroll
        for (int off = 16; off > 0; off >>= 1) {
            an += __shfl_down_sync(0xFFFFFFFFu, an, off);
            ad += __shfl_down_sync(0xFFFFFFFFu, ad, off);
        }
        int warp = tid >> 5, lane = tid & 31;
        if (lane == 0) { wn[warp] = an; wd[warp] = ad; }
        __syncthreads();
        if (tid == 0) {
            double n0 = 0.0, dd0 = 0.0, n1 = 0.0, dd1 = 0.0;
            #pragma unroll
            for (int j = 0; j < 8; ++j)  { n0 += wn[j]; dd0 += wd[j]; }
            #pragma unroll
            for (int j = 8; j < 16; ++j) { n1 += wn[j]; dd1 += wd[j]; }
            double acc = n0 / (dd0 + 1e-5) + n1 / (dd1 + 1e-5);
            out[0] = (float)(acc / (double)BB);
            g_count = 0;   // reset for next graph replay
        }
    }
}

extern "C" void kernel_launch(void* const* d_in, const int* in_sizes, int n_in,
                              void* d_out, int out_size) {
    const float* pred = (const float*)d_in[0];
    const float* tgt  = (const float*)d_in[1];
    (void)in_sizes; (void)n_in; (void)out_size;

    k_passBC<<<NPLANE * 3, 256>>>(tgt);                  // 384 blocks
    k_pass3<<<NBLK3, 512>>>(pred, tgt, (float*)d_out);   // 576 blocks
}

// round 7
// speedup vs baseline: 1.3038x; 1.1241x over previous
#include <cuda_runtime.h>
#include <math.h>

#define BB 2
#define DD 64
#define HH 96
#define WW 96
#define VOL (DD*HH*WW)          // 589824
#define NVOX (BB*VOL)           // 1179648
#define HWSZ (HH*WW)            // 9216
#define NPLANE (BB*DD)          // 128
#define BIGF 1e10f
#define WT 32

#define NBLK3 (BB*HH*(WW/WT))   // 576 pass3 blocks

// Scratch (device globals: allocation-free per harness rules)
__device__ float2 g_f2[NVOX];             // {fpos, fneg} after W+H transform
__device__ volatile float g_pn[NBLK3];
__device__ volatile float g_pd[NBLK3];
__device__ unsigned g_count;              // zero-init; last block resets -> deterministic

// Distance (voxels) from w (0..95) to nearest set bit of the 96-bit row mask
// {lo: bits 0-63, hi: bits 64-95}. Returns huge if none.
__device__ __forceinline__ int nearest_bit(unsigned long long lo, unsigned hi, int w) {
    const int INF = 1 << 30;
    int up = INF, down = INF;
    if (w < 64) {
        unsigned long long a = lo >> w;
        if (a) up = __ffsll((long long)a) - 1;
        else if (hi) up = (64 - w) + (__ffs((int)hi) - 1);
        unsigned long long b = lo << (63 - w);
        if (b) down = __clzll((long long)b);
    } else {
        int w2 = w - 64;
        unsigned a = hi >> w2;
        if (a) up = __ffs((int)a) - 1;
        unsigned b = hi << (31 - w2);
        if (b) down = __clz((int)b);
        else if (lo) down = (w2 + 1) + __clzll((long long)lo);
    }
    return (up < down) ? up : down;
}

// Fused: mask build (ballot) + pass1 (bit-scan along W, both phases)
// + pass2 (joint early-exit scan along H in smem). Block = (plane, w-tile).
__global__ __launch_bounds__(256) void k_passBC(const float* __restrict__ tgt) {
    __shared__ unsigned smask[HH][3];
    __shared__ float s1p[HH][WT];
    __shared__ float s1n[HH][WT];

    int wt = blockIdx.x % 3;
    int bd = blockIdx.x / 3;
    int base = bd * HWSZ;
    int tid = threadIdx.x;
    int lane = tid & 31;
    int warp = tid >> 5;              // 0..7

    // Build this plane's row masks: 288 warp-tasks over 8 warps (36 each).
    #pragma unroll 4
    for (int task = warp; task < HH * 3; task += 8) {
        int h = task / 3, seg = task % 3;
        float v = tgt[base + h * WW + seg * 32 + lane];
        unsigned m = __ballot_sync(0xFFFFFFFFu, v > 0.5f);
        if (lane == 0) smask[h][seg] = m;
    }
    __syncthreads();

    // pass1: exact distance along W via bit scan; both phases.
    #pragma unroll 1
    for (int v = tid; v < HH * WT; v += 256) {
        int h = v >> 5;
        int wl = v & 31;
        int w = wt * WT + wl;
        unsigned long long lo = (unsigned long long)smask[h][0]
                              | ((unsigned long long)smask[h][1] << 32);
        unsigned hi = smask[h][2];
        int dn = nearest_bit(lo, hi, w);        // nearest 1
        int dp = nearest_bit(~lo, ~hi, w);      // nearest 0
        s1p[h][wl] = (dp > 95) ? BIGF : (float)(dp * dp);
        s1n[h][wl] = (dn > 95) ? BIGF : (float)(dn * dn);
    }
    __syncthreads();

    // pass2 along H: joint early-exit windowed scan; write float2 coalesced.
    #pragma unroll 1
    for (int v = tid; v < HH * WT; v += 256) {
        int i = v >> 5;
        int wl = v & 31;
        float bp = s1p[i][wl];
        float bn = s1n[i][wl];
        #pragma unroll 1
        for (int k = 1; k < HH; ++k) {
            float k2 = (float)(k * k);
            if (k2 >= bp && k2 >= bn) break;
            int lo_ = i - k, hi_ = i + k;
            if (lo_ >= 0) {
                bp = fminf(bp, s1p[lo_][wl] + k2);
                bn = fminf(bn, s1n[lo_][wl] + k2);
            }
            if (hi_ < HH) {
                bp = fminf(bp, s1p[hi_][wl] + k2);
                bn = fminf(bn, s1n[hi_][wl] + k2);
            }
        }
        g_f2[base + i * WW + wt * WT + wl] = make_float2(bp, bn);
    }
}

// Pass3: along D in smem, fused loss epilogue + grid-final reduction.
// 256 threads (round-2 geometry, which measured best), MUFU-minimized epilogue.
__global__ __launch_bounds__(256) void k_pass3(const float* __restrict__ pred,
                                               const float* __restrict__ tgt,
                                               float* __restrict__ out) {
    __shared__ float sfp[DD][WT];
    __shared__ float sfn[DD][WT];
    __shared__ float rn[8], rd[8];
    __shared__ int s_last;

    int wt = blockIdx.x % (WW / WT);
    int bh = blockIdx.x / (WW / WT);
    int b = bh / HH;
    int h = bh % HH;
    int base = b * VOL + h * WW + wt * WT;
    int tid = threadIdx.x;

    #pragma unroll
    for (int r = tid; r < DD * WT; r += 256) {
        int d = r >> 5, w = r & 31;
        float2 v = g_f2[base + d * HWSZ + w];
        sfp[d][w] = v.x;
        sfn[d][w] = v.y;
    }
    __syncthreads();

    int w = tid & 31;
    int d0 = tid >> 5;  // 0..7
    float accn = 0.0f, accd = 0.0f;

    #pragma unroll 1
    for (int i = d0; i < DD; i += 8) {
        float bp = sfp[i][w];
        float bn = sfn[i][w];
        #pragma unroll 1
        for (int k = 1; k < DD; ++k) {
            float k2 = (float)(k * k);
            if (k2 >= bp && k2 >= bn) break;
            int lo = i - k, hi = i + k;
            if (lo >= 0) {
                bp = fminf(bp, sfp[lo][w] + k2);
                bn = fminf(bn, sfn[lo][w] + k2);
            }
            if (hi < DD) {
                bp = fminf(bp, sfp[hi][w] + k2);
                bn = fminf(bn, sfn[hi][w] + k2);
            }
        }
        // Exactly one of bp,bn is 0 => a = |dn-dp| = sqrt(max(bp,bn)).
        // sqrt needed only in the (3,5) band; boundaries agree by continuity.
        float m = fmaxf(bp, bn);
        float wgt;
        if (m <= 9.0f)       wgt = 1.0f;
        else if (m >= 25.0f) wgt = 0.0f;
        else                 wgt = 1.0f - (sqrtf(m) - 3.0f) * 0.5f;

        int idx = base + i * HWSZ + w;
        float p = pred[idx];
        float t = tgt[idx];
        // t is exactly 0 or 1: bce == -clamp(log(t ? p : 1-p), -100) bitwise.
        float pc = (t > 0.5f) ? p : (1.0f - p);
        float bce = -fmaxf(__logf(pc), -100.0f);
        accn += bce * wgt;
        accd += wgt;
    }

    #pragma unroll
    for (int off = 16; off > 0; off >>= 1) {
        accn += __shfl_down_sync(0xFFFFFFFFu, accn, off);
        accd += __shfl_down_sync(0xFFFFFFFFu, accd, off);
    }
    if (w == 0) { rn[d0] = accn; rd[d0] = accd; }
    __syncthreads();
    if (tid == 0) {
        float sn = 0.0f, sd = 0.0f;
        #pragma unroll
        for (int j = 0; j < 8; ++j) { sn += rn[j]; sd += rd[j]; }
        g_pn[blockIdx.x] = sn;
        g_pd[blockIdx.x] = sd;
        __threadfence();
        unsigned old = atomicAdd(&g_count, 1u);
        s_last = (old == NBLK3 - 1) ? 1 : 0;
    }
    __syncthreads();

    // Last block: reduce all 576 partials -> scalar, reset counter.
    if (s_last) {
        __shared__ double wn[8], wd[8];
        const int PER_B = NBLK3 / BB;     // 288
        int rb = tid >> 7;                // 0..1 (batch)
        int j0 = tid & 127;
        double an = 0.0, ad = 0.0;
        #pragma unroll
        for (int j = j0; j < PER_B; j += 128) {
            an += (double)g_pn[rb * PER_B + j];
            ad += (double)g_pd[rb * PER_B + j];
        }
        #pragma unroll
        for (int off = 16; off > 0; off >>= 1) {
            an += __shfl_down_sync(0xFFFFFFFFu, an, off);
            ad += __shfl_down_sync(0xFFFFFFFFu, ad, off);
        }
        int warp = tid >> 5, lane = tid & 31;
        if (lane == 0) { wn[warp] = an; wd[warp] = ad; }
        __syncthreads();
        if (tid == 0) {
            double n0 = 0.0, dd0 = 0.0, n1 = 0.0, dd1 = 0.0;
            #pragma unroll
            for (int j = 0; j < 4; ++j) { n0 += wn[j]; dd0 += wd[j]; }
            #pragma unroll
            for (int j = 4; j < 8; ++j) { n1 += wn[j]; dd1 += wd[j]; }
            double acc = n0 / (dd0 + 1e-5) + n1 / (dd1 + 1e-5);
            out[0] = (float)(acc / (double)BB);
            g_count = 0;   // reset for next graph replay
        }
    }
}

extern "C" void kernel_launch(void* const* d_in, const int* in_sizes, int n_in,
                              void* d_out, int out_size) {
    const float* pred = (const float*)d_in[0];
    const float* tgt  = (const float*)d_in[1];
    (void)in_sizes; (void)n_in; (void)out_size;

    k_passBC<<<NPLANE * 3, 256>>>(tgt);                  // 384 blocks
    k_pass3<<<NBLK3, 256>>>(pred, tgt, (float*)d_out);   // 576 blocks
}